// round 2
// baseline (speedup 1.0000x reference)
#include <cuda_runtime.h>
#include <cstdint>

// Problem constants: B=4, C=128, N=32*64*64=131072, E=128, H=4, hd=32,
// GN groups=8 (16 ch/group). Output (4,128) fp32.
#define NTOT 131072
#define CCH  128
#define BB   4
#define SCALE_ATTN 0.17677669529663687f   // 32^-0.5
#define EPSF 1e-5f

// ------------- device scratch (no allocations allowed) -------------
__device__ float d_part[512 * 2];        // per-(b,g,chunk) (sum, sumsq)
__device__ float d_wtil[2048];           // [b][h][c] = q^T Wk
__device__ float d_a[2048];              // [b][c][h]  logit weights
__device__ float d_alpha[512];           // [b][c] GN scale
__device__ float d_beta[512];            // [b][c] GN shift
__device__ float d_blk_m[512 * 4];       // per K2 block, per head: max logit
__device__ float d_blk_l[512 * 4];       // per K2 block, per head: sum exp
__device__ float d_blk_acc[512 * 512];   // per K2 block: [c*4+h] weighted raw sums
__device__ float d_y[2048];              // [b][h][c] attn-averaged x

// ------------- warp helpers -------------
__device__ __forceinline__ float warpSum(float v) {
#pragma unroll
    for (int o = 16; o; o >>= 1) v += __shfl_xor_sync(0xffffffffu, v, o);
    return v;
}
__device__ __forceinline__ float warpMax(float v) {
#pragma unroll
    for (int o = 16; o; o >>= 1) v = fmaxf(v, __shfl_xor_sync(0xffffffffu, v, o));
    return v;
}

// ============================================================================
// K1: group-norm statistics. grid = (b*8+g)*16 + chunk = 512 blocks, 256 thr.
// Each block: 16 channels x 8192 n positions -> (sum, sumsq) partial.
// ============================================================================
__global__ void __launch_bounds__(256) k_stats(const float* __restrict__ raw) {
    int bid = blockIdx.x;
    int ch  = bid & 15;          // chunk within n
    int bg  = bid >> 4;          // b*8 + g
    int t   = threadIdx.x;
    int w   = t >> 5, lane = t & 31;

    const float4* p = (const float4*)raw
                    + (size_t)bg * 16 * (NTOT / 4)   // start channel (b*128+g*16)
                    + (size_t)ch * (8192 / 4);       // chunk offset in n
    float s = 0.f, s2 = 0.f;
#pragma unroll 1
    for (int cl = 0; cl < 16; cl++) {
        const float4* rp = p + (size_t)cl * (NTOT / 4);
#pragma unroll
        for (int k = 0; k < 8; k++) {
            float4 v = rp[t + 256 * k];
            s  += (v.x + v.y) + (v.z + v.w);
            s2 += (v.x * v.x + v.y * v.y) + (v.z * v.z + v.w * v.w);
        }
    }
    s = warpSum(s); s2 = warpSum(s2);
    __shared__ float rs_[8], rs2_[8];
    if (lane == 0) { rs_[w] = s; rs2_[w] = s2; }
    __syncthreads();
    if (t == 0) {
        float S = 0.f, S2 = 0.f;
#pragma unroll
        for (int i = 0; i < 8; i++) { S += rs_[i]; S2 += rs2_[i]; }
        d_part[bid * 2]     = S;
        d_part[bid * 2 + 1] = S2;
    }
}

// ============================================================================
// K0: LayerNorm(e), q = eN @ Wq^T + bq, wtil[b,h,c] = sum_d q[b,h,d]*Wk[h*32+d,c]
// 1 block, 128 threads.
// ============================================================================
__global__ void __launch_bounds__(128) k_prep(
    const float* __restrict__ e,  const float* __restrict__ lng,
    const float* __restrict__ lnb, const float* __restrict__ Wq,
    const float* __restrict__ bq,  const float* __restrict__ Wk)
{
    __shared__ float en[512];    // [b][e]  normalized evolution feat
    __shared__ float qsh[512];   // [b][o]  query
    int t = threadIdx.x, w = t >> 5, lane = t & 31;

    // warp w handles batch w (4 warps, 4 batches)
    float v[4]; float s = 0.f, s2 = 0.f;
#pragma unroll
    for (int k = 0; k < 4; k++) {
        v[k] = e[w * 128 + lane + 32 * k];
        s += v[k]; s2 += v[k] * v[k];
    }
    s = warpSum(s); s2 = warpSum(s2);
    float mu  = s * (1.0f / 128.0f);
    float var = s2 * (1.0f / 128.0f) - mu * mu;
    float rs  = rsqrtf(var + EPSF);
#pragma unroll
    for (int k = 0; k < 4; k++) {
        int ee = lane + 32 * k;
        en[w * 128 + ee] = (v[k] - mu) * rs * lng[ee] + lnb[ee];
    }
    __syncthreads();

    // q[b][o], thread t -> o = t
    for (int b = 0; b < 4; b++) {
        float acc = bq[t];
#pragma unroll 4
        for (int ee = 0; ee < 128; ee++) acc = fmaf(en[b * 128 + ee], Wq[t * 128 + ee], acc);
        qsh[b * 128 + t] = acc;
    }
    __syncthreads();

    // wtil[b][h][c], thread t -> c = t
    for (int b = 0; b < 4; b++)
        for (int h = 0; h < 4; h++) {
            float acc = 0.f;
#pragma unroll 4
            for (int d = 0; d < 32; d++)
                acc = fmaf(qsh[b * 128 + h * 32 + d], Wk[(h * 32 + d) * 128 + t], acc);
            d_wtil[(b * 4 + h) * 128 + t] = acc;
        }
}

// ============================================================================
// K1b: reduce stats chunks -> (mu, rsqrt), build a / alpha / beta.
// 1 block, 128 threads.
// ============================================================================
__global__ void __launch_bounds__(128) k_finalize(
    const float* __restrict__ gng, const float* __restrict__ gnb)
{
    __shared__ float mus[32], rss[32];
    int t = threadIdx.x;
    if (t < 32) {   // t = b*8+g
        float s = 0.f, s2 = 0.f;
#pragma unroll
        for (int ch = 0; ch < 16; ch++) {
            s  += d_part[(t * 16 + ch) * 2];
            s2 += d_part[(t * 16 + ch) * 2 + 1];
        }
        const float inv = 1.0f / 2097152.0f;   // 16 * 131072
        float mu  = s * inv;
        float var = s2 * inv - mu * mu;
        mus[t] = mu;
        rss[t] = rsqrtf(var + EPSF);
    }
    __syncthreads();
    int c = t, g = c >> 4;
    for (int b = 0; b < 4; b++) {
        float rs = rss[b * 8 + g], mu = mus[b * 8 + g];
        float al = rs * gng[c];
        float be = gnb[c] - mu * al;
        d_alpha[b * 128 + c] = al;
        d_beta[b * 128 + c]  = be;
#pragma unroll
        for (int h = 0; h < 4; h++)
            d_a[(b * 128 + c) * 4 + h] = SCALE_ATTN * d_wtil[(b * 4 + h) * 128 + c] * al;
    }
}

// ============================================================================
// K2: main fused pass. grid = b*128 + chunk = 512 blocks, 128 threads.
// Chunk = 1024 contiguous n. Thread owns 8 n (two float4 quads).
// Pass A: logits (4 heads) per n.  Softmax (block-local, partials exported).
// Pass B: acc[h][c] += w[h][n]*raw[c][n] via warp reduction.
// ============================================================================
__global__ void __launch_bounds__(128) k_main(const float* __restrict__ raw) {
    __shared__ float a_sh[512];       // [c][h]
    __shared__ float red[16];         // [warp][h]
    __shared__ float pacc[4 * 512];   // [warp][c*4+h]

    int bid = blockIdx.x;
    int b = bid >> 7, ci = bid & 127;
    int t = threadIdx.x, w = t >> 5, lane = t & 31;

    ((float4*)a_sh)[t] = ((const float4*)d_a)[b * 128 + t];
    __syncthreads();

    const float4* base = (const float4*)raw
                       + (size_t)b * CCH * (NTOT / 4)
                       + (size_t)ci * (1024 / 4);

    // ---- Pass A: logits ----
    float lg[4][8];
#pragma unroll
    for (int h = 0; h < 4; h++)
#pragma unroll
        for (int j = 0; j < 8; j++) lg[h][j] = 0.f;

#pragma unroll 2
    for (int c = 0; c < 128; c++) {
        const float4* rp = base + (size_t)c * (NTOT / 4);
        float4 v0 = rp[2 * t];
        float4 v1 = rp[2 * t + 1];
        float4 aa = ((const float4*)a_sh)[c];
        float vv[8] = {v0.x, v0.y, v0.z, v0.w, v1.x, v1.y, v1.z, v1.w};
        float av[4] = {aa.x, aa.y, aa.z, aa.w};
#pragma unroll
        for (int h = 0; h < 4; h++)
#pragma unroll
            for (int j = 0; j < 8; j++) lg[h][j] = fmaf(av[h], vv[j], lg[h][j]);
    }

    // ---- block softmax ----
    float m[4];
#pragma unroll
    for (int h = 0; h < 4; h++) {
        float mt = lg[h][0];
#pragma unroll
        for (int j = 1; j < 8; j++) mt = fmaxf(mt, lg[h][j]);
        mt = warpMax(mt);
        if (lane == 0) red[w * 4 + h] = mt;
    }
    __syncthreads();
#pragma unroll
    for (int h = 0; h < 4; h++)
        m[h] = fmaxf(fmaxf(red[h], red[4 + h]), fmaxf(red[8 + h], red[12 + h]));
    __syncthreads();

    // w = exp(logit - m), reuse lg storage; l = sum
#pragma unroll
    for (int h = 0; h < 4; h++) {
        float s = 0.f;
#pragma unroll
        for (int j = 0; j < 8; j++) {
            lg[h][j] = __expf(lg[h][j] - m[h]);
            s += lg[h][j];
        }
        s = warpSum(s);
        if (lane == 0) red[w * 4 + h] = s;
    }
    __syncthreads();
    float lsum[4];
#pragma unroll
    for (int h = 0; h < 4; h++)
        lsum[h] = (red[h] + red[4 + h]) + (red[8 + h] + red[12 + h]);
    if (t < 4) {
        d_blk_m[bid * 4 + t] = m[t];
        d_blk_l[bid * 4 + t] = lsum[t];
    }

    // ---- Pass B: weighted raw accumulation ----
#pragma unroll 2
    for (int c = 0; c < 128; c++) {
        const float4* rp = base + (size_t)c * (NTOT / 4);
        float4 v0 = rp[2 * t];
        float4 v1 = rp[2 * t + 1];
        float vv[8] = {v0.x, v0.y, v0.z, v0.w, v1.x, v1.y, v1.z, v1.w};
        float4 pt;
        float p0 = 0.f, p1 = 0.f, p2 = 0.f, p3 = 0.f;
#pragma unroll
        for (int j = 0; j < 8; j++) {
            p0 = fmaf(lg[0][j], vv[j], p0);
            p1 = fmaf(lg[1][j], vv[j], p1);
            p2 = fmaf(lg[2][j], vv[j], p2);
            p3 = fmaf(lg[3][j], vv[j], p3);
        }
        pt.x = warpSum(p0); pt.y = warpSum(p1);
        pt.z = warpSum(p2); pt.w = warpSum(p3);
        if (lane == 0) *((float4*)&pacc[w * 512 + c * 4]) = pt;
    }
    __syncthreads();
#pragma unroll
    for (int r = 0; r < 4; r++) {
        int i = t + 128 * r;
        float s = (pacc[i] + pacc[512 + i]) + (pacc[1024 + i] + pacc[1536 + i]);
        d_blk_acc[(size_t)bid * 512 + i] = s;
    }
}

// ============================================================================
// K3a: combine per-block softmax partials -> y[b][h][c]. grid 16 (b*4+h), 128 thr.
// ============================================================================
__global__ void __launch_bounds__(128) k_combine() {
    __shared__ float sm[128], sl[128], sf[128];
    int bh = blockIdx.x, b = bh >> 2, h = bh & 3;
    int t = threadIdx.x;   // c, and loader index ci
    sm[t] = d_blk_m[(b * 128 + t) * 4 + h];
    sl[t] = d_blk_l[(b * 128 + t) * 4 + h];
    __syncthreads();
    float M = -3.0e38f;
#pragma unroll 8
    for (int i = 0; i < 128; i++) M = fmaxf(M, sm[i]);
    sf[t] = __expf(sm[t] - M);
    __syncthreads();
    float L = 0.f;
#pragma unroll 8
    for (int i = 0; i < 128; i++) L = fmaf(sl[i], sf[i], L);
    float r = 0.f;
#pragma unroll 4
    for (int ci = 0; ci < 128; ci++)
        r = fmaf(d_blk_acc[(size_t)(b * 128 + ci) * 512 + (t << 2) + h], sf[ci], r);
    r /= L;
    d_y[(b * 4 + h) * 128 + t] = d_alpha[b * 128 + t] * r + d_beta[b * 128 + t];
}

// ============================================================================
// K3b: o1 = Wv@y + bv (per head), out = Wo@o1 + bo. 1 block, 128 threads.
// ============================================================================
__global__ void __launch_bounds__(128) k_out(
    const float* __restrict__ Wv, const float* __restrict__ bv,
    const float* __restrict__ Wo, const float* __restrict__ bo,
    float* __restrict__ out)
{
    __shared__ float o1[512];
    int t = threadIdx.x;
    int h = t >> 5;
    for (int b = 0; b < 4; b++) {
        float acc = bv[t];
#pragma unroll 4
        for (int c = 0; c < 128; c++)
            acc = fmaf(Wv[t * 128 + c], d_y[(b * 4 + h) * 128 + c], acc);
        o1[b * 128 + t] = acc;
    }
    __syncthreads();
    for (int b = 0; b < 4; b++) {
        float acc = bo[t];
#pragma unroll 4
        for (int c = 0; c < 128; c++)
            acc = fmaf(Wo[t * 128 + c], o1[b * 128 + c], acc);
        out[b * 128 + t] = acc;
    }
}

// ============================================================================
extern "C" void kernel_launch(void* const* d_in, const int* in_sizes, int n_in,
                              void* d_out, int out_size) {
    const float* raw = (const float*)d_in[0];   // diff_spatial (4,128,32,64,64)
    const float* evo = (const float*)d_in[1];   // evolution_feat (4,128)
    const float* lng = (const float*)d_in[2];   // ln_g
    const float* lnb = (const float*)d_in[3];   // ln_b
    const float* gng = (const float*)d_in[4];   // gn_g
    const float* gnb = (const float*)d_in[5];   // gn_b
    const float* Wq  = (const float*)d_in[6];
    const float* bq  = (const float*)d_in[7];
    const float* Wk  = (const float*)d_in[8];
    // d_in[9] = bk: cancels in softmax, unused
    const float* Wv  = (const float*)d_in[10];
    const float* bv  = (const float*)d_in[11];
    const float* Wo  = (const float*)d_in[12];
    const float* bo  = (const float*)d_in[13];
    float* out = (float*)d_out;

    k_stats<<<512, 256>>>(raw);
    k_prep<<<1, 128>>>(evo, lng, lnb, Wq, bq, Wk);
    k_finalize<<<1, 128>>>(gng, gnb);
    k_main<<<512, 128>>>(raw);
    k_combine<<<16, 128>>>();
    k_out<<<1, 128>>>(Wv, bv, Wo, bo, out);
}